// round 9
// baseline (speedup 1.0000x reference)
#include <cuda_runtime.h>
#include <math.h>

#define Cn 256
#define Hn 50
#define Wn 76
#define SCALE 0.0625f
#define Sn (Hn * Wn)               // 3800
#define PLANE Sn
#define BATCH_ELEMS (Cn * Sn)      // 972800
#define NUM_ROIS 128

// channel-major scratch: [B][S][C]  (7.78 MB, static device array — no allocation)
__device__ float g_feat_t[2 * BATCH_ELEMS];

// ---------------- transpose: [C][S] -> [S][C], per batch ----------------
__global__ __launch_bounds__(256)
void transpose_kernel(const float* __restrict__ feat)
{
    __shared__ float tile[32][33];
    const int b  = blockIdx.z;
    const int s0 = blockIdx.x * 32;
    const int c0 = blockIdx.y * 32;
    const int tx = threadIdx.x, ty = threadIdx.y;

    const float* src = feat + b * BATCH_ELEMS;
    float*       dst = g_feat_t + b * BATCH_ELEMS;

    #pragma unroll
    for (int k = 0; k < 32; k += 8) {
        int s = s0 + tx;
        if (s < Sn)
            tile[ty + k][tx] = __ldg(src + (c0 + ty + k) * Sn + s);
    }
    __syncthreads();
    #pragma unroll
    for (int k = 0; k < 32; k += 8) {
        int s = s0 + ty + k;
        if (s < Sn)
            dst[s * Cn + c0 + tx] = tile[tx][ty + k];
    }
}

// ---------------- pool: block = (roi, channel-half), warp = 32 channels ----------------
__global__ __launch_bounds__(128)
void roipool_kernel(const float* __restrict__ rois,
                    float* __restrict__ out)
{
    __shared__ float stage[4 * 32 * 49];   // 25,088 B
    __shared__ unsigned int win[49];
    __shared__ int sb;

    const int bid  = blockIdx.x;
    const int tid  = threadIdx.x;
    const int wid  = tid >> 5;
    const int lane = tid & 31;
    const int roi  = bid >> 1;
    const int half = bid & 1;

    // geometry: one bin per thread (threads 0..48)
    if (tid < 49) {
        const int ph = tid / 7;
        const int pw = tid - ph * 7;
        const float* r = rois + roi * 5;
        int b  = (int)rintf(r[0]);
        int x1 = (int)rintf(r[1] * SCALE);
        int y1 = (int)rintf(r[2] * SCALE);
        int x2 = (int)rintf(r[3] * SCALE);
        int y2 = (int)rintf(r[4] * SCALE);

        int eh = max(y2 - y1 + 1, 1);
        int ew = max(x2 - x1 + 1, 1);

        // bit-exact emulation of XLA-CPU fast-math reference: extent * fl(1/7)
        const float R7 = 0.14285714285714285f;
        float bh = __fmul_rn((float)eh, R7);
        float bw = __fmul_rn((float)ew, R7);

        int hs = min(max((int)floorf(__fmul_rn((float)ph,       bh)) + y1, 0), Hn);
        int he = min(max((int)ceilf (__fmul_rn((float)(ph + 1), bh)) + y1, 0), Hn);
        int ws = min(max((int)floorf(__fmul_rn((float)pw,       bw)) + x1, 0), Wn);
        int we = min(max((int)ceilf (__fmul_rn((float)(pw + 1), bw)) + x1, 0), Wn);

        unsigned int empty = (hs >= he || ws >= we) ? 1u : 0u;
        win[tid] = (unsigned)hs | ((unsigned)he << 8) |
                   ((unsigned)ws << 16) | ((unsigned)we << 24) | (empty << 31);
        if (tid == 0) sb = b * BATCH_ELEMS;
    }
    __syncthreads();

    const int chgrp = half * 4 + wid;            // 0..7
    const int ch    = chgrp * 32 + lane;
    const float* bt = g_feat_t + sb + ch;        // lane-contiguous per cell

    // 49 bins, uniform across the warp: zero divergence, 1 wavefront per cell load
    float* st = stage + (wid * 32 + lane) * 49;  // store stride 49 (odd): conflict-free
    for (int bin = 0; bin < 49; ++bin) {
        const unsigned int wv = win[bin];
        float m = 0.0f;
        if (!(wv >> 31)) {
            const int hs = wv & 0xff;
            const int he = (wv >> 8) & 0xff;
            const int ws = (wv >> 16) & 0xff;
            const int we = (wv >> 24) & 0x7f;
            m = -INFINITY;
            for (int h = hs; h < he; ++h) {
                const float* p = bt + (h * Wn + ws) * Cn;
                for (int w = ws; w < we; ++w, p += Cn)
                    m = fmaxf(m, __ldg(p));
            }
        }
        st[bin] = m;
    }
    __syncwarp();

    // coalesced write-out: this warp owns 32 channels x 49 bins = 1568 contiguous floats
    const float* s = stage + wid * 32 * 49;      // read contiguous: conflict-free
    float* o = out + (roi * Cn + chgrp * 32) * 49;
    #pragma unroll 7
    for (int it = 0; it < 49; ++it) {
        int j = it * 32 + lane;
        o[j] = s[j];
    }
}

extern "C" void kernel_launch(void* const* d_in, const int* in_sizes, int n_in,
                              void* d_out, int out_size)
{
    const float* feat = (const float*)d_in[0];
    const float* rois = (const float*)d_in[1];
    float* out = (float*)d_out;

    dim3 tgrid((Sn + 31) / 32, Cn / 32, 2);      // 119 x 8 x 2
    transpose_kernel<<<tgrid, dim3(32, 8)>>>(feat);
    roipool_kernel<<<NUM_ROIS * 2, 128>>>(rois, out);
}

// round 12
// speedup vs baseline: 4.2095x; 4.2095x over previous
#include <cuda_runtime.h>
#include <math.h>

#define Cn 256
#define Hn 50
#define Wn 76
#define SCALE 0.0625f
#define Sn (Hn * Wn)               // 3800
#define BATCH_ELEMS (Cn * Sn)      // 972800
#define NUM_ROIS 128

// channel-major scratch: [B][S][C]  (7.78 MB static device array — no allocation)
__device__ float g_feat_t[2 * BATCH_ELEMS];

// ---------------- transpose: [C][S] -> [S][C], per batch ----------------
__global__ __launch_bounds__(256)
void transpose_kernel(const float* __restrict__ feat)
{
    __shared__ float tile[32][33];
    const int b  = blockIdx.z;
    const int s0 = blockIdx.x * 32;
    const int c0 = blockIdx.y * 32;
    const int tx = threadIdx.x, ty = threadIdx.y;

    const float* src = feat + b * BATCH_ELEMS;
    float*       dst = g_feat_t + b * BATCH_ELEMS;

    #pragma unroll
    for (int k = 0; k < 32; k += 8) {
        int s = s0 + tx;
        if (s < Sn)
            tile[ty + k][tx] = __ldg(src + (c0 + ty + k) * Sn + s);
    }
    __syncthreads();
    #pragma unroll
    for (int k = 0; k < 32; k += 8) {
        int s = s0 + ty + k;
        if (s < Sn)
            dst[s * Cn + c0 + tx] = tile[tx][ty + k];
    }
}

// ------------- pool: block = (roi, 32-ch group), 8 warps, warp-uniform bins -------------
__global__ __launch_bounds__(256)
void roipool_kernel(const float* __restrict__ rois,
                    float* __restrict__ out)
{
    __shared__ float stage[32 * 49];          // 6.3 KB: [ch_local][bin]
    __shared__ unsigned int win[49];
    __shared__ int sb;

    const int bid   = blockIdx.x;
    const int tid   = threadIdx.x;
    const int wid   = tid >> 5;
    const int lane  = tid & 31;
    const int roi   = bid >> 3;               // 8 blocks per ROI
    const int chgrp = bid & 7;                // 32-channel group

    // ---- geometry: one bin per thread (threads 0..48) ----
    if (tid < 49) {
        const int ph = tid / 7;
        const int pw = tid - ph * 7;
        const float* r = rois + roi * 5;
        int b  = (int)rintf(r[0]);
        int x1 = (int)rintf(r[1] * SCALE);
        int y1 = (int)rintf(r[2] * SCALE);
        int x2 = (int)rintf(r[3] * SCALE);
        int y2 = (int)rintf(r[4] * SCALE);

        int eh = max(y2 - y1 + 1, 1);
        int ew = max(x2 - x1 + 1, 1);

        // bit-exact emulation of XLA-CPU fast-math reference: extent * fl(1/7)
        const float R7 = 0.14285714285714285f;
        float bh = __fmul_rn((float)eh, R7);
        float bw = __fmul_rn((float)ew, R7);

        int hs = min(max((int)floorf(__fmul_rn((float)ph,       bh)) + y1, 0), Hn);
        int he = min(max((int)ceilf (__fmul_rn((float)(ph + 1), bh)) + y1, 0), Hn);
        int ws = min(max((int)floorf(__fmul_rn((float)pw,       bw)) + x1, 0), Wn);
        int we = min(max((int)ceilf (__fmul_rn((float)(pw + 1), bw)) + x1, 0), Wn);

        unsigned int empty = (hs >= he || ws >= we) ? 1u : 0u;
        win[tid] = (unsigned)hs | ((unsigned)he << 8) |
                   ((unsigned)ws << 16) | ((unsigned)we << 24) | (empty << 31);
        if (tid == 0) sb = b * BATCH_ELEMS;
    }
    __syncthreads();

    const float* bt = g_feat_t + sb + chgrp * 32 + lane;   // lane-contiguous per cell

    // warp handles bins wid, wid+8, ... : window uniform across warp, loads 1 wavefront/cell
    for (int bin = wid; bin < 49; bin += 8) {
        const unsigned int wv = win[bin];
        float m = 0.0f;
        if (!(wv >> 31)) {
            const int hs = wv & 0xff;
            const int he = (wv >> 8) & 0xff;
            const int ws = (wv >> 16) & 0xff;
            const int we = (wv >> 24) & 0x7f;
            m = -INFINITY;
            for (int h = hs; h < he; ++h) {
                const float* p = bt + (h * Wn + ws) * Cn;
                for (int w = ws; w < we; ++w, p += Cn)
                    m = fmaxf(m, __ldg(p));
            }
        }
        stage[lane * 49 + bin] = m;           // stride 49 (odd): conflict-free
    }
    __syncthreads();

    // coalesced write-out: 1568 contiguous floats for (roi, chgrp)
    float* o = out + (roi * Cn + chgrp * 32) * 49;
    for (int j = tid; j < 32 * 49; j += 256)
        o[j] = stage[j];
}

extern "C" void kernel_launch(void* const* d_in, const int* in_sizes, int n_in,
                              void* d_out, int out_size)
{
    const float* feat = (const float*)d_in[0];
    const float* rois = (const float*)d_in[1];
    float* out = (float*)d_out;

    dim3 tgrid((Sn + 31) / 32, Cn / 32, 2);   // 119 x 8 x 2
    transpose_kernel<<<tgrid, dim3(32, 8)>>>(feat);
    roipool_kernel<<<NUM_ROIS * 8, 256>>>(rois, out);
}

// round 16
// speedup vs baseline: 5.2338x; 1.2433x over previous
#include <cuda_runtime.h>
#include <math.h>

#define Cn 256
#define Hn 50
#define Wn 76
#define SCALE 0.0625f
#define Sn (Hn * Wn)               // 3800
#define BATCH_ELEMS (Cn * Sn)      // 972800
#define NUM_ROIS 128
#define WROW (Wn * Cn)             // row stride in transposed layout

// channel-major scratch: [B][S][C]  (7.78 MB static device array — no allocation)
__device__ float g_feat_t[2 * BATCH_ELEMS];

// ---------------- transpose: [C][S] -> [S][C], per batch ----------------
__global__ __launch_bounds__(256)
void transpose_kernel(const float* __restrict__ feat)
{
    __shared__ float tile[32][33];
    const int b  = blockIdx.z;
    const int s0 = blockIdx.x * 32;
    const int c0 = blockIdx.y * 32;
    const int tx = threadIdx.x, ty = threadIdx.y;

    const float* src = feat + b * BATCH_ELEMS;
    float*       dst = g_feat_t + b * BATCH_ELEMS;

    #pragma unroll
    for (int k = 0; k < 32; k += 8) {
        int s = s0 + tx;
        if (s < Sn)
            tile[ty + k][tx] = __ldg(src + (c0 + ty + k) * Sn + s);
    }
    __syncthreads();
    #pragma unroll
    for (int k = 0; k < 32; k += 8) {
        int s = s0 + ty + k;
        if (s < Sn)
            dst[s * Cn + c0 + tx] = tile[tx][ty + k];
    }
}

// ------------- pool: block = (roi, 32-ch group), warp-uniform branch-free 4x4 -------------
__global__ __launch_bounds__(256)
void roipool_kernel(const float* __restrict__ rois,
                    float* __restrict__ out)
{
    __shared__ float stage[32 * 49];          // [ch_local][bin], stride 49 conflict-free
    __shared__ unsigned int win[49];
    __shared__ int sb;

    const int bid   = blockIdx.x;
    const int tid   = threadIdx.x;
    const int wid   = tid >> 5;
    const int lane  = tid & 31;
    const int roi   = bid >> 3;               // 8 blocks per ROI
    const int chgrp = bid & 7;

    // ---- geometry: one bin per thread (threads 0..48) ----
    if (tid < 49) {
        const int ph = tid / 7;
        const int pw = tid - ph * 7;
        const float* r = rois + roi * 5;
        int b  = (int)rintf(r[0]);
        int x1 = (int)rintf(r[1] * SCALE);
        int y1 = (int)rintf(r[2] * SCALE);
        int x2 = (int)rintf(r[3] * SCALE);
        int y2 = (int)rintf(r[4] * SCALE);

        int eh = max(y2 - y1 + 1, 1);
        int ew = max(x2 - x1 + 1, 1);

        // bit-exact emulation of XLA-CPU fast-math reference: extent * fl(1/7)
        const float R7 = 0.14285714285714285f;
        float bh = __fmul_rn((float)eh, R7);
        float bw = __fmul_rn((float)ew, R7);

        int hs = min(max((int)floorf(__fmul_rn((float)ph,       bh)) + y1, 0), Hn);
        int he = min(max((int)ceilf (__fmul_rn((float)(ph + 1), bh)) + y1, 0), Hn);
        int ws = min(max((int)floorf(__fmul_rn((float)pw,       bw)) + x1, 0), Wn);
        int we = min(max((int)ceilf (__fmul_rn((float)(pw + 1), bw)) + x1, 0), Wn);

        unsigned int empty = (hs >= he || ws >= we) ? 1u : 0u;
        if (empty) { hs = 0; he = 1; ws = 0; we = 1; }   // safe dummy window

        win[tid] = (unsigned)hs | ((unsigned)he << 8) |
                   ((unsigned)ws << 16) | ((unsigned)we << 24) | (empty << 31);
        if (tid == 0) sb = b * BATCH_ELEMS;
    }
    __syncthreads();

    const float* bt = g_feat_t + sb + chgrp * 32 + lane;   // lane-contiguous per cell

    // warp handles bins wid, wid+8, ...  Window uniform across warp; span <= 4x4.
    // Branch-free clamped 16-load pattern: all loads independent (MLP=16),
    // each exactly one 128B wavefront.
    for (int bin = wid; bin < 49; bin += 8) {
        const unsigned int wv = win[bin];
        const int hs = wv & 0xff;
        const int he = (wv >> 8) & 0xff;
        const int ws = (wv >> 16) & 0xff;
        const int we = (wv >> 24) & 0x7f;
        const unsigned int empty = wv >> 31;

        const int H1 = he - 1 - hs;            // 0..3
        const int W1 = we - 1 - ws;            // 0..3
        const int dh1 = min(1, H1) * WROW;
        const int dh2 = min(2, H1) * WROW;
        const int dh3 = H1 * WROW;
        const int dw1 = min(1, W1) * Cn;
        const int dw2 = min(2, W1) * Cn;
        const int dw3 = W1 * Cn;

        const float* p0 = bt + (hs * Wn + ws) * Cn;
        float a0 = __ldg(p0);
        float a1 = __ldg(p0 + dw1);
        float a2 = __ldg(p0 + dw2);
        float a3 = __ldg(p0 + dw3);
        const float* p1 = p0 + dh1;
        float b0 = __ldg(p1);
        float b1 = __ldg(p1 + dw1);
        float b2 = __ldg(p1 + dw2);
        float b3 = __ldg(p1 + dw3);
        const float* p2 = p0 + dh2;
        float c0 = __ldg(p2);
        float c1 = __ldg(p2 + dw1);
        float c2 = __ldg(p2 + dw2);
        float c3 = __ldg(p2 + dw3);
        const float* p3 = p0 + dh3;
        float d0 = __ldg(p3);
        float d1 = __ldg(p3 + dw1);
        float d2 = __ldg(p3 + dw2);
        float d3 = __ldg(p3 + dw3);

        float r0 = fmaxf(fmaxf(a0, a1), fmaxf(a2, a3));
        float r1 = fmaxf(fmaxf(b0, b1), fmaxf(b2, b3));
        float r2 = fmaxf(fmaxf(c0, c1), fmaxf(c2, c3));
        float r3 = fmaxf(fmaxf(d0, d1), fmaxf(d2, d3));
        float m  = fmaxf(fmaxf(r0, r1), fmaxf(r2, r3));

        stage[lane * 49 + bin] = empty ? 0.0f : m;
    }
    __syncthreads();

    // coalesced write-out: 1568 contiguous floats for (roi, chgrp)
    float* o = out + (roi * Cn + chgrp * 32) * 49;
    for (int j = tid; j < 32 * 49; j += 256)
        o[j] = stage[j];
}

extern "C" void kernel_launch(void* const* d_in, const int* in_sizes, int n_in,
                              void* d_out, int out_size)
{
    const float* feat = (const float*)d_in[0];
    const float* rois = (const float*)d_in[1];
    float* out = (float*)d_out;

    dim3 tgrid((Sn + 31) / 32, Cn / 32, 2);   // 119 x 8 x 2
    transpose_kernel<<<tgrid, dim3(32, 8)>>>(feat);
    roipool_kernel<<<NUM_ROIS * 8, 256>>>(rois, out);
}